// round 8
// baseline (speedup 1.0000x reference)
#include <cuda_runtime.h>

// Depthwise 3x3 conv, stride 1, VALID, fp32.
// x: (16, 64, 512, 512), w: (64, 3, 3), out: (16, 64, 510, 510).
//
// R7: 330 us, DRAM 83.8%, traffic already at the 2.14 GB minimum. Remaining
// losses are scheduling: ~13 waves (12 transitions x ~2360 cyc) and 17408
// latency-exposed ring-fill prologues.
// R8: one block per plane (grid=1024, CHUNK=510). All blocks resident
// (residency cap 9/SM x 148 = 1332 >= 1024) -> zero wave transitions, one
// prologue per plane, fully sequential per-plane streaming.

namespace {

constexpr int CH  = 64;
constexpr int H   = 512;
constexpr int W   = 512;
constexpr int OH  = 510;   // 510 = 6 * 85
constexpr int OW  = 510;
constexpr int TPB = 128;   // 128 threads * 4 outputs = 512 >= OW

__global__ __launch_bounds__(TPB)
void dwconv3x3_kernel(const float* __restrict__ x,
                      const float* __restrict__ wgt,
                      float* __restrict__ out)
{
    const int plane = blockIdx.x;              // n*CH + c
    const int c     = plane & (CH - 1);

    const float* __restrict__ in = x + (size_t)plane * (H * W);
    float* __restrict__ op       = out + (size_t)plane * (OH * OW);

    const float* wp = wgt + c * 9;
    const float w00 = __ldg(wp + 0), w01 = __ldg(wp + 1), w02 = __ldg(wp + 2);
    const float w10 = __ldg(wp + 3), w11 = __ldg(wp + 4), w12 = __ldg(wp + 5);
    const float w20 = __ldg(wp + 6), w21 = __ldg(wp + 7), w22 = __ldg(wp + 8);

    const int x0   = threadIdx.x * 4;          // 0, 4, ..., 508
    const int lane = threadIdx.x & 31;

    // 6-row ring of 6-column strips; fully unrolled -> all registers.
    float r[6][6];

    // One float4 per row per thread; halo cols 4,5 shuffled from lane+1
    // (its a.x, a.y). Lane 31 (warp boundary) loads its own float2 halo.
    auto load_row = [&](float* d, int y) {
        const float4 a = *reinterpret_cast<const float4*>(in + y * W + x0);
        d[0] = a.x; d[1] = a.y; d[2] = a.z; d[3] = a.w;
        d[4] = __shfl_down_sync(0xffffffffu, a.x, 1);
        d[5] = __shfl_down_sync(0xffffffffu, a.y, 1);
        if (lane == 31) {
            if (x0 + 4 < W) {
                const float2 b = *reinterpret_cast<const float2*>(in + y * W + x0 + 4);
                d[4] = b.x; d[5] = b.y;
            } else {
                d[4] = 0.f; d[5] = 0.f;        // x0 == 508: cols 512/513 unused
            }
        }
    };

    // Output row y from rows a (y), b (y+1), cc (y+2). AL16: row byte offset
    // 2040*y is 16B-aligned iff y even; stage parity == row parity (y0 = 0).
    // Streaming stores keep L2 clean for reads.
    auto proc = [&](const float* a, const float* b, const float* cc, int y,
                    bool al16) {
        float o[4];
        #pragma unroll
        for (int j = 0; j < 4; ++j) {
            float s;
            s = a[j]      * w00;
            s = fmaf(a[j + 1],  w01, s);
            s = fmaf(a[j + 2],  w02, s);
            s = fmaf(b[j],      w10, s);
            s = fmaf(b[j + 1],  w11, s);
            s = fmaf(b[j + 2],  w12, s);
            s = fmaf(cc[j],     w20, s);
            s = fmaf(cc[j + 1], w21, s);
            s = fmaf(cc[j + 2], w22, s);
            o[j] = s;
        }
        float* orow = op + (size_t)y * OW + x0;
        if (x0 + 4 <= OW) {
            if (al16) {
                __stcs(reinterpret_cast<float4*>(orow),
                       make_float4(o[0], o[1], o[2], o[3]));
            } else {
                __stcs(reinterpret_cast<float2*>(orow),     make_float2(o[0], o[1]));
                __stcs(reinterpret_cast<float2*>(orow) + 1, make_float2(o[2], o[3]));
            }
        } else {                                // x0 == 508: only 508/509 valid
            __stcs(reinterpret_cast<float2*>(orow), make_float2(o[0], o[1]));
        }
    };

    // Prologue: rows 0..5.
    #pragma unroll
    for (int k = 0; k < 6; ++k)
        load_row(r[k], k);

    int y = 0;
    // 84 main iterations: 6 output rows each + prefetch of the next 6 input
    // rows (load at stage k consumed 4 stages later).
    #pragma unroll 1
    for (int i = 0; i < OH / 6 - 1; ++i) {
        proc(r[0], r[1], r[2], y + 0, true ); load_row(r[0], y + 6);
        proc(r[1], r[2], r[3], y + 1, false); load_row(r[1], y + 7);
        proc(r[2], r[3], r[4], y + 2, true ); load_row(r[2], y + 8);
        proc(r[3], r[4], r[5], y + 3, false); load_row(r[3], y + 9);
        proc(r[4], r[5], r[0], y + 4, true ); load_row(r[4], y + 10);
        proc(r[5], r[0], r[1], y + 5, false); load_row(r[5], y + 11);
        y += 6;
    }

    // Epilogue (y = 504): only rows 510, 511 still needed (stages 4/5).
    proc(r[0], r[1], r[2], y + 0, true ); load_row(r[0], y + 6);
    proc(r[1], r[2], r[3], y + 1, false); load_row(r[1], y + 7);
    proc(r[2], r[3], r[4], y + 2, true );
    proc(r[3], r[4], r[5], y + 3, false);
    proc(r[4], r[5], r[0], y + 4, true );
    proc(r[5], r[0], r[1], y + 5, false);
}

} // namespace

extern "C" void kernel_launch(void* const* d_in, const int* in_sizes, int n_in,
                              void* d_out, int out_size)
{
    const float* x = (const float*)d_in[0];
    const float* w = (const float*)d_in[1];
    float* out     = (float*)d_out;

    const int planes = in_sizes[0] / (H * W);   // 16 * 64 = 1024
    dwconv3x3_kernel<<<planes, TPB>>>(x, w, out);
}

// round 9
// speedup vs baseline: 1.2484x; 1.2484x over previous
#include <cuda_runtime.h>

// Depthwise 3x3 conv, stride 1, VALID, fp32.
// x: (16, 64, 512, 512), w: (64, 3, 3), out: (16, 64, 510, 510).
//
// R8 (1 block/plane) FALSIFIED the wave-transition theory: occ 38.6% ->
// DRAM 67.9%. DRAM feed is occupancy-coupled here. Revert to R7 structure
// (CHUNK=30, grid 17408, DRAM 83.8% @ occ 52.7%).
// R9: __launch_bounds__(128, 10) caps regs at 51 -> 10 resident blocks/SM
// (40 warps, occ 62.5%) to push DRAM busy further up the occupancy curve.

namespace {

constexpr int CH    = 64;
constexpr int H     = 512;
constexpr int W     = 512;
constexpr int OH    = 510;
constexpr int OW    = 510;
constexpr int CHUNK = 30;    // 17 chunks * 30 = 510; multiple of 6
constexpr int TPB   = 128;   // 128 threads * 4 outputs = 512 >= OW

__global__ __launch_bounds__(TPB, 10)
void dwconv3x3_kernel(const float* __restrict__ x,
                      const float* __restrict__ wgt,
                      float* __restrict__ out)
{
    const int plane = blockIdx.y;              // n*CH + c   (slow axis)
    const int c     = plane & (CH - 1);
    const int y0    = blockIdx.x * CHUNK;      // chunk = fast axis -> adjacent
                                               // chunks of a plane co-resident
    const float* __restrict__ in = x + (size_t)plane * (H * W);
    float* __restrict__ op       = out + (size_t)plane * (OH * OW);

    const float* wp = wgt + c * 9;
    const float w00 = __ldg(wp + 0), w01 = __ldg(wp + 1), w02 = __ldg(wp + 2);
    const float w10 = __ldg(wp + 3), w11 = __ldg(wp + 4), w12 = __ldg(wp + 5);
    const float w20 = __ldg(wp + 6), w21 = __ldg(wp + 7), w22 = __ldg(wp + 8);

    const int x0   = threadIdx.x * 4;          // 0, 4, ..., 508
    const int lane = threadIdx.x & 31;

    // 6-row ring of 6-column strips; fully unrolled -> all registers.
    float r[6][6];

    // One float4 per row per thread; halo cols 4,5 shuffled from lane+1
    // (its a.x, a.y). Lane 31 (warp boundary) loads its own float2 halo.
    auto load_row = [&](float* d, int y) {
        const float4 a = *reinterpret_cast<const float4*>(in + y * W + x0);
        d[0] = a.x; d[1] = a.y; d[2] = a.z; d[3] = a.w;
        d[4] = __shfl_down_sync(0xffffffffu, a.x, 1);
        d[5] = __shfl_down_sync(0xffffffffu, a.y, 1);
        if (lane == 31) {
            if (x0 + 4 < W) {
                const float2 b = *reinterpret_cast<const float2*>(in + y * W + x0 + 4);
                d[4] = b.x; d[5] = b.y;
            } else {
                d[4] = 0.f; d[5] = 0.f;        // x0 == 508: cols 512/513 unused
            }
        }
    };

    // Output row y from rows a (y), b (y+1), cc (y+2). AL16: row byte offset
    // 2040*y is 16B-aligned iff y even; stage parity == row parity (y0 even).
    // Streaming stores keep L2 clean for input-halo reuse.
    auto proc = [&](const float* a, const float* b, const float* cc, int y,
                    bool al16) {
        float o[4];
        #pragma unroll
        for (int j = 0; j < 4; ++j) {
            float s;
            s = a[j]      * w00;
            s = fmaf(a[j + 1],  w01, s);
            s = fmaf(a[j + 2],  w02, s);
            s = fmaf(b[j],      w10, s);
            s = fmaf(b[j + 1],  w11, s);
            s = fmaf(b[j + 2],  w12, s);
            s = fmaf(cc[j],     w20, s);
            s = fmaf(cc[j + 1], w21, s);
            s = fmaf(cc[j + 2], w22, s);
            o[j] = s;
        }
        float* orow = op + (size_t)y * OW + x0;
        if (x0 + 4 <= OW) {
            if (al16) {
                __stcs(reinterpret_cast<float4*>(orow),
                       make_float4(o[0], o[1], o[2], o[3]));
            } else {
                __stcs(reinterpret_cast<float2*>(orow),     make_float2(o[0], o[1]));
                __stcs(reinterpret_cast<float2*>(orow) + 1, make_float2(o[2], o[3]));
            }
        } else {                                // x0 == 508: only 508/509 valid
            __stcs(reinterpret_cast<float2*>(orow), make_float2(o[0], o[1]));
        }
    };

    // Prologue: rows y0 .. y0+5 (y0 <= 480 -> max row 485, in bounds).
    #pragma unroll
    for (int k = 0; k < 6; ++k)
        load_row(r[k], y0 + k);

    int y = y0;
    // Each iter: 6 output rows + prefetch of the next 6 input rows
    // (load at stage k consumed 4 stages later).
    #pragma unroll 1
    for (int i = 0; i < CHUNK / 6 - 1; ++i) {
        proc(r[0], r[1], r[2], y + 0, true ); load_row(r[0], y + 6);
        proc(r[1], r[2], r[3], y + 1, false); load_row(r[1], y + 7);
        proc(r[2], r[3], r[4], y + 2, true ); load_row(r[2], y + 8);
        proc(r[3], r[4], r[5], y + 3, false); load_row(r[3], y + 9);
        proc(r[4], r[5], r[0], y + 4, true ); load_row(r[4], y + 10);
        proc(r[5], r[0], r[1], y + 5, false); load_row(r[5], y + 11);
        y += 6;
    }

    // Epilogue: only rows y+6, y+7 still needed (stages 4/5).
    // y+7 = y0+31 <= 511 for the last chunk — in bounds, no clamps.
    proc(r[0], r[1], r[2], y + 0, true ); load_row(r[0], y + 6);
    proc(r[1], r[2], r[3], y + 1, false); load_row(r[1], y + 7);
    proc(r[2], r[3], r[4], y + 2, true );
    proc(r[3], r[4], r[5], y + 3, false);
    proc(r[4], r[5], r[0], y + 4, true );
    proc(r[5], r[0], r[1], y + 5, false);
}

} // namespace

extern "C" void kernel_launch(void* const* d_in, const int* in_sizes, int n_in,
                              void* d_out, int out_size)
{
    const float* x = (const float*)d_in[0];
    const float* w = (const float*)d_in[1];
    float* out     = (float*)d_out;

    const int planes = in_sizes[0] / (H * W);   // 16 * 64 = 1024
    dim3 grid(OH / CHUNK, planes);              // (17, 1024) — chunk fastest
    dwconv3x3_kernel<<<grid, TPB>>>(x, w, out);
}